// round 3
// baseline (speedup 1.0000x reference)
#include <cuda_runtime.h>
#include <cstdint>

// Problem constants (upper bounds; runtime shapes read from in_sizes)
#define NMAX 16384
#define PMAX 4096

typedef unsigned long long u64;
typedef unsigned int u32;

// Cross-kernel scratch (allocation-free per harness rules)
__device__ unsigned short g_writer[PMAX];     // last writer item per slot, 0xFFFF = original pool row
__device__ float          g_p2_scores[NMAX];  // compacted phase-2 scores, in item order
__device__ unsigned short g_p2_item[NMAX];    // original item index per phase-2 entry
__device__ int            g_T;                // number of phase-2 entries
__device__ int            g_final_count;      // final pool count

__device__ __forceinline__ u64 umin64(u64 a, u64 b) { return a < b ? a : b; }

__device__ __forceinline__ u64 min8(const u64* ch) {
    u64 a = umin64(ch[0], ch[1]);
    u64 b = umin64(ch[2], ch[3]);
    u64 c = umin64(ch[4], ch[5]);
    u64 d = umin64(ch[6], ch[7]);
    return umin64(umin64(a, b), umin64(c, d));
}

// min over 8 children with child `self` replaced by `rep` (loads are
// address-independent of values -> can issue before the compare chain)
__device__ __forceinline__ u64 min8rep(const u64* ch, int self, u64 rep) {
    u64 v0 = (self == 0) ? rep : ch[0];
    u64 v1 = (self == 1) ? rep : ch[1];
    u64 v2 = (self == 2) ? rep : ch[2];
    u64 v3 = (self == 3) ? rep : ch[3];
    u64 v4 = (self == 4) ? rep : ch[4];
    u64 v5 = (self == 5) ? rep : ch[5];
    u64 v6 = (self == 6) ? rep : ch[6];
    u64 v7 = (self == 7) ? rep : ch[7];
    u64 a = umin64(v0, v1);
    u64 b = umin64(v2, v3);
    u64 c = umin64(v4, v5);
    u64 d = umin64(v6, v7);
    return umin64(umin64(a, b), umin64(c, d));
}

// ---------------------------------------------------------------------------
// Kernel 1: single block. Prefix-scan of valid flags (score > 0.5).
// Valid item with exclusive rank r: appends at slot C0+r iff C0+r < P,
// else becomes phase-2 entry q = r - (P - C0).
// ---------------------------------------------------------------------------
__global__ __launch_bounds__(1024, 1)
void k_classify(const float* __restrict__ scores, const int* __restrict__ countp,
                int N, int P) {
    __shared__ int warp_sums[32];
    const int tid = threadIdx.x;
    const int C0 = *countp;
    const int ipt = (N + blockDim.x - 1) / blockDim.x;
    const int start = tid * ipt;
    const int end = min(start + ipt, N);

    // init writer sentinel (ordered before scatter by the __syncthreads below)
    for (int i = tid; i < P; i += blockDim.x) g_writer[i] = 0xFFFFu;

    int c = 0;
    for (int i = start; i < end; ++i) c += (scores[i] > 0.5f) ? 1 : 0;

    // block exclusive scan
    const int lane = tid & 31, wid = tid >> 5;
    int v = c;
    #pragma unroll
    for (int o = 1; o < 32; o <<= 1) {
        int t = __shfl_up_sync(0xFFFFFFFFu, v, o);
        if (lane >= o) v += t;
    }
    if (lane == 31) warp_sums[wid] = v;
    __syncthreads();
    if (wid == 0) {
        int nw = blockDim.x >> 5;
        int w = (lane < nw) ? warp_sums[lane] : 0;
        #pragma unroll
        for (int o = 1; o < 32; o <<= 1) {
            int t = __shfl_up_sync(0xFFFFFFFFu, w, o);
            if (lane >= o) w += t;
        }
        warp_sums[lane] = w;
    }
    __syncthreads();

    const int excl = (v - c) + ((wid > 0) ? warp_sums[wid - 1] : 0);
    const int total = warp_sums[(blockDim.x >> 5) - 1];
    int room = P - C0; if (room < 0) room = 0;

    if (tid == 0) {
        int appended = (total < room) ? total : room;
        g_T = total - appended;
        g_final_count = C0 + appended;
    }

    int r = excl;
    for (int i = start; i < end; ++i) {
        if (scores[i] > 0.5f) {
            if (r < room) {
                g_writer[C0 + r] = (unsigned short)i;
            } else {
                int q = r - room;
                g_p2_scores[q] = scores[i];
                g_p2_item[q]   = (unsigned short)i;
            }
            r++;
        }
    }
}

// ---------------------------------------------------------------------------
// Kernel 2: single block. Exact sequential simulation of the replace phase
// over an 8-ary min-tournament tree of keys (float_bits << 32) | slot.
// u64 min == (min value, then min slot) == jnp.argmin first-index semantics.
// All compared values are >= 0 so float bit patterns are order-monotone.
// Writes final priorities + count to d_out tail; writer map for kernel 3.
// ---------------------------------------------------------------------------
__global__ __launch_bounds__(1024, 1)
void k_sim(const float* __restrict__ scores,
           const float* __restrict__ priorities,
           float* __restrict__ out,
           int P, int D, long long out_size) {
    extern __shared__ unsigned char smem[];
    u64* leaf = (u64*)smem;                               // PMAX
    u64* L1   = leaf + PMAX;                              // 512
    u64* L2   = L1 + 512;                                 // 64
    u64* L3   = L2 + 64;                                  // 8
    unsigned short* wr = (unsigned short*)(L3 + 8);       // PMAX
    float* ps = (float*)(wr + PMAX);                      // NMAX
    unsigned short* pi = (unsigned short*)(ps + NMAX);    // NMAX

    const int tid = threadIdx.x;
    const int nthr = blockDim.x;

    // Leaves: appended slots take their score as priority; others keep input
    // priorities (zeros for never-filled slots). Pad beyond P with +inf keys.
    for (int i = tid; i < PMAX; i += nthr) {
        u64 key;
        unsigned short w = 0xFFFFu;
        if (i < P) {
            w = g_writer[i];
            float pv = (w != 0xFFFFu) ? scores[w] : priorities[i];
            key = ((u64)__float_as_uint(pv) << 32) | (u32)i;
        } else {
            key = ~0ull;
        }
        leaf[i] = key;
        wr[i] = w;
    }
    const int T = g_T;
    for (int q = tid; q < T; q += nthr) { ps[q] = g_p2_scores[q]; pi[q] = g_p2_item[q]; }
    __syncthreads();
    for (int j = tid; j < 512; j += nthr) L1[j] = min8(leaf + j * 8);
    __syncthreads();
    for (int j = tid; j < 64; j += nthr) L2[j] = min8(L1 + j * 8);
    __syncthreads();
    if (tid < 8) L3[tid] = min8(L2 + tid * 8);
    __syncthreads();

    if (tid == 0) {
        u64 root = min8(L3);
        float rootval = __uint_as_float((u32)(root >> 32));

        const int Tm = T & ~3;
        for (int q0 = 0; q0 < Tm; q0 += 4) {
            float4 s4 = *(const float4*)(ps + q0);  // ps is 16B aligned
            #pragma unroll
            for (int k = 0; k < 4; ++k) {
                float s = (k == 0) ? s4.x : (k == 1) ? s4.y : (k == 2) ? s4.z : s4.w;
                if (s > rootval) {
                    u32 slot = (u32)root;
                    wr[slot] = pi[q0 + k];
                    u64 nk = ((u64)__float_as_uint(s) << 32) | slot;
                    int n1 = slot >> 3, s0 = slot & 7;
                    int n2 = n1 >> 3,   s1 = n1 & 7;
                    int n3 = n2 >> 3,   s2 = n2 & 7;
                    u64 m1 = min8rep(leaf + (n1 << 3), s0, nk);
                    u64 m2 = min8rep(L1   + (n2 << 3), s1, m1);
                    u64 m3 = min8rep(L2   + (n3 << 3), s2, m2);
                    root    = min8rep(L3, n3, m3);
                    leaf[slot] = nk; L1[n1] = m1; L2[n2] = m2; L3[n3] = m3;
                    rootval = __uint_as_float((u32)(root >> 32));
                }
            }
        }
        for (int q = Tm; q < T; ++q) {
            float s = ps[q];
            if (s > rootval) {
                u32 slot = (u32)root;
                wr[slot] = pi[q];
                u64 nk = ((u64)__float_as_uint(s) << 32) | slot;
                int n1 = slot >> 3, s0 = slot & 7;
                int n2 = n1 >> 3,   s1 = n1 & 7;
                int n3 = n2 >> 3,   s2 = n2 & 7;
                u64 m1 = min8rep(leaf + (n1 << 3), s0, nk);
                u64 m2 = min8rep(L1   + (n2 << 3), s1, m1);
                u64 m3 = min8rep(L2   + (n3 << 3), s2, m2);
                root    = min8rep(L3, n3, m3);
                leaf[slot] = nk; L1[n1] = m1; L2[n2] = m2; L3[n3] = m3;
                rootval = __uint_as_float((u32)(root >> 32));
            }
        }
    }
    __syncthreads();

    // Epilogue: writer map to global; priorities + count to output tail.
    const long long base = (long long)P * (long long)D;
    for (int i = tid; i < P; i += nthr) {
        g_writer[i] = wr[i];
        if (base + i < out_size)
            out[base + i] = __uint_as_float((u32)(leaf[i] >> 32));
    }
    if (tid == 0 && base + P < out_size)
        out[base + P] = (float)g_final_count;
}

// ---------------------------------------------------------------------------
// Kernel 3: parallel row gather. One block per pool slot: copy either the
// original pool row or the last-writing summary row into the output.
// ---------------------------------------------------------------------------
__global__ void k_copy(const float* __restrict__ pool,
                       const float* __restrict__ summaries,
                       float* __restrict__ out, int D) {
    const int row = blockIdx.x;
    const unsigned short w = g_writer[row];
    const float* src = (w == 0xFFFFu) ? (pool + (long long)row * D)
                                      : (summaries + (long long)w * D);
    float* dst = out + (long long)row * D;
    if ((D & 3) == 0) {
        const float4* s4 = (const float4*)src;
        float4* d4 = (float4*)dst;
        for (int i = threadIdx.x; i < (D >> 2); i += blockDim.x) d4[i] = s4[i];
    } else {
        for (int i = threadIdx.x; i < D; i += blockDim.x) dst[i] = src[i];
    }
}

// ---------------------------------------------------------------------------
// Inputs (metadata order): summaries[N,D] f32, scores[N] f32, pool[P,D] f32,
// priorities[P] f32, count i32 scalar.
// Output: concat(pool_out[P*D], priorities[P], count) as f32.
// ---------------------------------------------------------------------------
extern "C" void kernel_launch(void* const* d_in, const int* in_sizes, int n_in,
                              void* d_out, int out_size) {
    const float* summaries  = (const float*)d_in[0];
    const float* scores     = (const float*)d_in[1];
    const float* pool       = (const float*)d_in[2];
    const float* priorities = (const float*)d_in[3];
    const int*   countp     = (const int*)d_in[4];

    const int N = in_sizes[1];
    const int P = in_sizes[3];
    const int D = (N > 0) ? (in_sizes[0] / N) : 0;
    float* out = (float*)d_out;

    // shared: leaves 32KB + tree 4.7KB + writer 8KB + staged scores 64KB + items 32KB
    const int smem_bytes = PMAX * 8 + 512 * 8 + 64 * 8 + 8 * 8 + PMAX * 2
                         + NMAX * 4 + NMAX * 2;  // = 143936
    cudaFuncSetAttribute(k_sim, cudaFuncAttributeMaxDynamicSharedMemorySize, smem_bytes);

    k_classify<<<1, 1024>>>(scores, countp, N, P);
    k_sim<<<1, 1024, smem_bytes>>>(scores, priorities, out, P, D, (long long)out_size);
    k_copy<<<P, 256>>>(pool, summaries, out, D);
}

// round 4
// speedup vs baseline: 5.4306x; 5.4306x over previous
#include <cuda_runtime.h>
#include <cstdint>

// Problem constants (upper bounds; runtime shapes read from in_sizes)
#define NMAX 16384
#define PMAX 4096
#define NB   65536           // rank buckets
#define TREE_LEAVES 4096     // binary loser tree leaves (== PMAX)

typedef unsigned long long u64;
typedef unsigned int u32;
typedef unsigned short u16;

// -------- cross-kernel scratch (allocation-free: __device__ globals) --------
__device__ u16 g_writer[PMAX];        // last writer item per slot, 0xFFFF = keep original
__device__ u16 g_p2_item[NMAX];       // phase-2 item indices, in arrival order
__device__ int g_T;                   // number of phase-2 entries
__device__ int g_final_count;         // final pool count

__device__ u32 g_hist[NB];            // bucket histogram
__device__ u32 g_prefix[NB];          // exclusive prefix of hist
__device__ u32 g_cursor[NB];          // scatter cursors (init = prefix)
__device__ u32 g_bdata[NMAX + PMAX];  // ordered-key values grouped by bucket
__device__ u16 g_rank_scores[NMAX];   // exact dense-ish rank of each score
__device__ u16 g_rank_prior[PMAX];    // exact rank of each input priority

// order-preserving u32 transform of float (total order matching IEEE <)
__device__ __forceinline__ u32 okey(float v) {
    u32 b = __float_as_uint(v);
    return (b & 0x80000000u) ? ~b : (b | 0x80000000u);
}
// monotone bucketing (exactness NOT required; monotone + equal-on-equal is)
__device__ __forceinline__ int bucketOf(float v) {
    if (!(v > 0.0f)) return 0;
    if (v >= 1.0f)   return NB - 1;
    int b = (int)(v * 65536.0f);
    return b < 0 ? 0 : (b > NB - 1 ? NB - 1 : b);
}

// ---------------------------------------------------------------------------
// Rank pipeline: hist -> scan -> scatter -> per-value rank
// rank(v) = #{candidate u : u < v}, candidates = scores[0..N) ∪ priorities[0..P)
// ---------------------------------------------------------------------------
__global__ void k_zero() {
    int i = blockIdx.x * blockDim.x + threadIdx.x;
    if (i < NB) g_hist[i] = 0u;
}

__global__ void k_hist(const float* __restrict__ scores,
                       const float* __restrict__ priorities, int N, int P) {
    int i = blockIdx.x * blockDim.x + threadIdx.x;
    if (i >= N + P) return;
    float v = (i < N) ? scores[i] : priorities[i - N];
    atomicAdd(&g_hist[bucketOf(v)], 1u);
}

__global__ __launch_bounds__(1024, 1) void k_scan() {
    __shared__ u32 wsum[32];
    const int tid = threadIdx.x;
    const int CPT = NB / 1024;            // 64 per thread
    const int base = tid * CPT;
    u32 s = 0;
    #pragma unroll 8
    for (int j = 0; j < CPT; ++j) s += g_hist[base + j];

    const int lane = tid & 31, wid = tid >> 5;
    u32 v = s;
    #pragma unroll
    for (int o = 1; o < 32; o <<= 1) {
        u32 t = __shfl_up_sync(0xFFFFFFFFu, v, o);
        if (lane >= o) v += t;
    }
    if (lane == 31) wsum[wid] = v;
    __syncthreads();
    if (wid == 0) {
        u32 w = wsum[lane];
        #pragma unroll
        for (int o = 1; o < 32; o <<= 1) {
            u32 t = __shfl_up_sync(0xFFFFFFFFu, w, o);
            if (lane >= o) w += t;
        }
        wsum[lane] = w;
    }
    __syncthreads();
    u32 run = (v - s) + ((wid > 0) ? wsum[wid - 1] : 0u);
    #pragma unroll 8
    for (int j = 0; j < CPT; ++j) {
        u32 h = g_hist[base + j];
        g_prefix[base + j] = run;
        g_cursor[base + j] = run;
        run += h;
    }
}

__global__ void k_scatter(const float* __restrict__ scores,
                          const float* __restrict__ priorities, int N, int P) {
    int i = blockIdx.x * blockDim.x + threadIdx.x;
    if (i >= N + P) return;
    float v = (i < N) ? scores[i] : priorities[i - N];
    u32 pos = atomicAdd(&g_cursor[bucketOf(v)], 1u);
    g_bdata[pos] = okey(v);
}

__global__ void k_rank(const float* __restrict__ scores,
                       const float* __restrict__ priorities, int N, int P) {
    int i = blockIdx.x * blockDim.x + threadIdx.x;
    if (i >= N + P) return;
    float v = (i < N) ? scores[i] : priorities[i - N];
    int b = bucketOf(v);
    u32 k = okey(v);
    u32 base = g_prefix[b];
    u32 n = g_hist[b];
    u32 c = 0;
    for (u32 j = 0; j < n; ++j) c += (g_bdata[base + j] < k) ? 1u : 0u;
    u16 r = (u16)(base + c);   // < N+P <= 20480 < 2^15
    if (i < N) g_rank_scores[i] = r; else g_rank_prior[i - N] = r;
}

// ---------------------------------------------------------------------------
// Classify: prefix-scan valid flags (score > 0.5). First `room` valid items
// append in order at slots C0..; the rest become phase-2 entries.
// ---------------------------------------------------------------------------
__global__ __launch_bounds__(1024, 1)
void k_classify(const float* __restrict__ scores, const int* __restrict__ countp,
                int N, int P) {
    __shared__ int warp_sums[32];
    const int tid = threadIdx.x;
    const int C0 = *countp;
    const int ipt = (N + blockDim.x - 1) / blockDim.x;
    const int start = tid * ipt;
    const int end = min(start + ipt, N);

    for (int i = tid; i < P; i += blockDim.x) g_writer[i] = 0xFFFFu;

    int c = 0;
    for (int i = start; i < end; ++i) c += (scores[i] > 0.5f) ? 1 : 0;

    const int lane = tid & 31, wid = tid >> 5;
    int v = c;
    #pragma unroll
    for (int o = 1; o < 32; o <<= 1) {
        int t = __shfl_up_sync(0xFFFFFFFFu, v, o);
        if (lane >= o) v += t;
    }
    if (lane == 31) warp_sums[wid] = v;
    __syncthreads();
    if (wid == 0) {
        int nw = blockDim.x >> 5;
        int w = (lane < nw) ? warp_sums[lane] : 0;
        #pragma unroll
        for (int o = 1; o < 32; o <<= 1) {
            int t = __shfl_up_sync(0xFFFFFFFFu, w, o);
            if (lane >= o) w += t;
        }
        warp_sums[lane] = w;
    }
    __syncthreads();

    const int excl = (v - c) + ((wid > 0) ? warp_sums[wid - 1] : 0);
    const int total = warp_sums[(blockDim.x >> 5) - 1];
    int room = P - C0; if (room < 0) room = 0;

    if (tid == 0) {
        int appended = (total < room) ? total : room;
        g_T = total - appended;
        g_final_count = C0 + appended;
    }

    int r = excl;
    for (int i = start; i < end; ++i) {
        if (scores[i] > 0.5f) {
            if (r < room) g_writer[C0 + r] = (u16)i;
            else          g_p2_item[r - room] = (u16)i;
            r++;
        }
    }
}

// ---------------------------------------------------------------------------
// Sim: exact sequential replace-phase over a binary LOSER TREE of u32 keys
//   key = (rank << 12) | slot  -> umin32 == (min value, min slot) == argmin.
// Phase-2 stream packed as e = (rank << 14) | item; insert iff
//   e >= th where th = (rootrank+1)<<14  (<=> rank > rootrank <=> s > min).
// ---------------------------------------------------------------------------
__global__ __launch_bounds__(1024, 1)
void k_sim(const float* __restrict__ scores,
           const float* __restrict__ priorities,
           float* __restrict__ out,
           int N, int P, int D, long long out_size) {
    extern __shared__ u32 sm4[];
    u32* pe     = sm4;                        // NMAX+8 (16B aligned for uint4)
    u32* lk     = pe + (NMAX + 8);            // TREE_LEAVES leaf keys (build only)
    u32* win    = lk + TREE_LEAVES;           // TREE_LEAVES winner temp (build only)
    u32* intr   = win + TREE_LEAVES;          // TREE_LEAVES loser nodes [1..4095]
    u16* wr     = (u16*)(intr + TREE_LEAVES); // PMAX writer map

    const int tid = threadIdx.x;
    const int nthr = blockDim.x;
    const int T = g_T;
    const int Tpad = (T + 7) & ~7;

    // leaf keys + writer map
    for (int i = tid; i < TREE_LEAVES; i += nthr) {
        u32 key = 0xFFFFFFFFu;
        u16 w = 0xFFFFu;
        if (i < P) {
            w = g_writer[i];
            u32 rk = (w != 0xFFFFu) ? (u32)g_rank_scores[w] : (u32)g_rank_prior[i];
            key = (rk << 12) | (u32)i;
        }
        lk[i] = key;
        wr[i] = w;
    }
    // packed phase-2 stream (padded with 0 -> always skipped since th >= 1<<14)
    for (int q = tid; q < Tpad; q += nthr) {
        u32 e = 0;
        if (q < T) {
            u32 it = (u32)g_p2_item[q];
            e = ((u32)g_rank_scores[it] << 14) | it;
        }
        pe[q] = e;
    }
    __syncthreads();

    // build loser tree: leaves are virtual nodes [4096,8192); internal [1,4096)
    for (int n = 2048 + tid; n < 4096; n += nthr) {
        u32 a = lk[(n - 2048) * 2], b = lk[(n - 2048) * 2 + 1];
        win[n] = min(a, b);
        intr[n] = max(a, b);
    }
    __syncthreads();
    for (int sz = 1024; sz >= 1; sz >>= 1) {
        for (int n = sz + tid; n < 2 * sz; n += nthr) {
            u32 a = win[2 * n], b = win[2 * n + 1];
            win[n] = min(a, b);
            intr[n] = max(a, b);
        }
        __syncthreads();
    }

    if (tid == 0 && T > 0) {
        u32 root = win[1];
        u32 th = ((root >> 12) + 1u) << 14;
        const uint4* pe4 = (const uint4*)pe;

        for (int q0 = 0; q0 < Tpad; q0 += 8) {
            uint4 A = pe4[q0 >> 2];
            uint4 B = pe4[(q0 >> 2) + 1];
            u32 mx = max(max(max(A.x, A.y), max(A.z, A.w)),
                         max(max(B.x, B.y), max(B.z, B.w)));
            if (mx < th) continue;   // threshold only rises -> conservative skip OK
            u32 ev[8] = {A.x, A.y, A.z, A.w, B.x, B.y, B.z, B.w};
            #pragma unroll
            for (int k = 0; k < 8; ++k) {
                u32 e = ev[k];
                if (e >= th) {
                    u32 slot = root & 0xFFFu;
                    wr[slot] = (u16)(e & 0x3FFFu);
                    u32 w = ((e >> 14) << 12) | slot;   // new key at winner leaf
                    int nb = (int)slot + TREE_LEAVES;
                    u32 l[12], so[12];
                    #pragma unroll
                    for (int d = 1; d <= 12; ++d) l[d - 1] = intr[nb >> d];  // all loads up front
                    #pragma unroll
                    for (int d = 0; d < 12; ++d) {      // replay matches up the path
                        u32 t = l[d];
                        u32 nw = min(w, t);
                        so[d] = max(w, t);
                        w = nw;
                    }
                    #pragma unroll
                    for (int d = 1; d <= 12; ++d) intr[nb >> d] = so[d - 1];
                    root = w;
                    th = ((root >> 12) + 1u) << 14;
                }
            }
        }
    }
    __syncthreads();

    // epilogue: writer map out; priorities + count to output tail
    const long long base = (long long)P * (long long)D;
    for (int i = tid; i < P; i += nthr) {
        u16 w = wr[i];
        g_writer[i] = w;
        if (base + i < out_size)
            out[base + i] = (w != 0xFFFFu) ? scores[w] : priorities[i];
    }
    if (tid == 0 && base + P < out_size)
        out[base + P] = (float)g_final_count;
}

// ---------------------------------------------------------------------------
// Row gather: one block per pool slot, copy original pool row or last-writing
// summary row into the output.
// ---------------------------------------------------------------------------
__global__ void k_copy(const float* __restrict__ pool,
                       const float* __restrict__ summaries,
                       float* __restrict__ out, int D) {
    const int row = blockIdx.x;
    const u16 w = g_writer[row];
    const float* src = (w == 0xFFFFu) ? (pool + (long long)row * D)
                                      : (summaries + (long long)w * D);
    float* dst = out + (long long)row * D;
    if ((D & 3) == 0) {
        const float4* s4 = (const float4*)src;
        float4* d4 = (float4*)dst;
        for (int i = threadIdx.x; i < (D >> 2); i += blockDim.x) d4[i] = s4[i];
    } else {
        for (int i = threadIdx.x; i < D; i += blockDim.x) dst[i] = src[i];
    }
}

// ---------------------------------------------------------------------------
// Inputs (metadata order): summaries[N,D] f32, scores[N] f32, pool[P,D] f32,
// priorities[P] f32, count i32 scalar.
// Output: concat(pool_out[P*D], priorities[P], count) as f32.
// ---------------------------------------------------------------------------
extern "C" void kernel_launch(void* const* d_in, const int* in_sizes, int n_in,
                              void* d_out, int out_size) {
    const float* summaries  = (const float*)d_in[0];
    const float* scores     = (const float*)d_in[1];
    const float* pool       = (const float*)d_in[2];
    const float* priorities = (const float*)d_in[3];
    const int*   countp     = (const int*)d_in[4];

    const int N = in_sizes[1];
    const int P = in_sizes[3];
    const int D = (N > 0) ? (in_sizes[0] / N) : 0;
    const int M = N + P;
    float* out = (float*)d_out;

    const int sim_smem = (NMAX + 8 + 3 * TREE_LEAVES) * 4 + TREE_LEAVES * 2; // 122912
    static int attr_done = 0;
    if (!attr_done) {
        cudaFuncSetAttribute(k_sim, cudaFuncAttributeMaxDynamicSharedMemorySize, sim_smem);
        attr_done = 1;
    }

    k_zero   <<<NB / 256, 256>>>();
    k_hist   <<<(M + 255) / 256, 256>>>(scores, priorities, N, P);
    k_scan   <<<1, 1024>>>();
    k_scatter<<<(M + 255) / 256, 256>>>(scores, priorities, N, P);
    k_rank   <<<(M + 255) / 256, 256>>>(scores, priorities, N, P);
    k_classify<<<1, 1024>>>(scores, countp, N, P);
    k_sim    <<<1, 1024, sim_smem>>>(scores, priorities, out, N, P, D, (long long)out_size);
    k_copy   <<<P, 256>>>(pool, summaries, out, D);
}